// round 2
// baseline (speedup 1.0000x reference)
#include <cuda_runtime.h>
#include <cstdint>

#define N      8192
#define NNZv   262144
#define NSEEDS 256
#define SAMP   7372            /* int(N * 0.9) */

// ---------------- scratch (device globals; no allocation allowed) ----------
__device__ int           g_seed0[N];
__device__ int           g_mask1[N];
__device__ int           g_masknodes[N];
__device__ float         g_deg[N];
__device__ float         g_norm[N];
__device__ int           g_maskidx[N];
__device__ int           g_temnum;
__device__ unsigned char g_keep[NNZv];

// ---------------- Threefry-2x32 (exact JAX reference rounds) ---------------
__host__ __device__ __forceinline__ void threefry(uint32_t key0, uint32_t key1,
                                                  uint32_t x0, uint32_t x1,
                                                  uint32_t &o0, uint32_t &o1) {
    uint32_t ks0 = key0, ks1 = key1, ks2 = key0 ^ key1 ^ 0x1BD11BDAu;
    x0 += ks0; x1 += ks1;
#define TF_ROT(v,d) (((v) << (d)) | ((v) >> (32 - (d))))
#define TF_R(r) { x0 += x1; x1 = TF_ROT(x1, r); x1 ^= x0; }
    TF_R(13) TF_R(15) TF_R(26) TF_R(6)   x0 += ks1; x1 += ks2 + 1u;
    TF_R(17) TF_R(29) TF_R(16) TF_R(24)  x0 += ks2; x1 += ks0 + 2u;
    TF_R(13) TF_R(15) TF_R(26) TF_R(6)   x0 += ks0; x1 += ks1 + 3u;
    TF_R(17) TF_R(29) TF_R(16) TF_R(24)  x0 += ks1; x1 += ks2 + 4u;
    TF_R(13) TF_R(15) TF_R(26) TF_R(6)   x0 += ks2; x1 += ks0 + 5u;
    o0 = x0; o1 = x1;
#undef TF_R
#undef TF_ROT
}

// bits -> uniform float32 in [0,1), exact JAX formula
__device__ __forceinline__ float bits_to_uniform(uint32_t b) {
    return __uint_as_float((b >> 9) | 0x3F800000u) - 1.0f;
}

// ---------------- kernels --------------------------------------------------
__global__ void k_init() {
    int i = blockIdx.x * blockDim.x + threadIdx.x;
    if (i < N) { g_seed0[i] = 0; g_mask1[i] = 0; g_masknodes[i] = 0; g_deg[i] = 0.0f; }
}

__global__ void k_seed(const int* __restrict__ seeds) {
    int i = threadIdx.x;
    if (i < NSEEDS) { int s = seeds[i]; g_seed0[s] = 1; g_masknodes[s] = 1; }
}

// depth-0: incident edges removed; mark both endpoints as next frontier
__global__ void k_bfs0(const int* __restrict__ rows, const int* __restrict__ cols) {
    int e = blockIdx.x * blockDim.x + threadIdx.x;
    if (e >= NNZv) return;
    int r = rows[e], c = cols[e];
    bool inc = (g_seed0[r] | g_seed0[c]) != 0;
    g_keep[e] = inc ? 0 : 1;
    if (inc) { g_mask1[r] = 1; g_mask1[c] = 1; }
}

// depth-1: remove edges touching frontier; accumulate row degree for survivors
__global__ void k_bfs1_deg(const int* __restrict__ rows, const int* __restrict__ cols,
                           const float* __restrict__ comp) {
    int e = blockIdx.x * blockDim.x + threadIdx.x;
    if (e >= NNZv) return;
    if (!g_keep[e]) return;
    int r = rows[e], c = cols[e];
    if (g_mask1[r] | g_mask1[c]) { g_keep[e] = 0; return; }
    atomicAdd(&g_deg[r], comp[(size_t)r * N + c]);
}

// random node sampling: samped[i] = random_bits(k2_inner)[i] % 8192 (partitionable mode)
__global__ void k_samp(uint32_t t0, uint32_t t1) {
    int i = blockIdx.x * blockDim.x + threadIdx.x;
    if (i >= SAMP) return;
    uint32_t a, b; threefry(t0, t1, 0u, (uint32_t)i, a, b);
    g_masknodes[(a ^ b) & (N - 1)] = 1;
}

__global__ void k_norm() {
    int i = blockIdx.x * blockDim.x + threadIdx.x;
    if (i < N) g_norm[i] = rsqrtf(g_deg[i] + 1e-12f);
}

// compacting prefix scan over (masknodes | mask1) -> g_maskidx, g_temnum
__global__ void k_scan() {
    __shared__ int s[1024];
    int t = threadIdx.x;
    int base = t * 8;
    int bits = 0, loc = 0;
#pragma unroll
    for (int i = 0; i < 8; i++) {
        int m = (g_masknodes[base + i] | g_mask1[base + i]) ? 1 : 0;
        bits |= m << i; loc += m;
    }
    s[t] = loc; __syncthreads();
    for (int off = 1; off < 1024; off <<= 1) {
        int v = (t >= off) ? s[t - off] : 0;
        __syncthreads();
        s[t] += v;
        __syncthreads();
    }
    int pos = s[t] - loc;            // exclusive prefix
    if (t == 1023) g_temnum = s[1023];
#pragma unroll
    for (int i = 0; i < 8; i++)
        if ((bits >> i) & 1) g_maskidx[pos++] = base + i;
}

__global__ void k_zero(float4* __restrict__ out, int n4) {
    int i = blockIdx.x * blockDim.x + threadIdx.x;
    if (i < n4) out[i] = make_float4(0.f, 0.f, 0.f, 0.f);
}

// kept edges -> enc (normalized) and dec; diagonal -> dec
__global__ void k_edges(const int* __restrict__ rows, const int* __restrict__ cols,
                        const float* __restrict__ comp,
                        float* __restrict__ enc, float* __restrict__ dec) {
    int e = blockIdx.x * blockDim.x + threadIdx.x;
    if (e >= NNZv) return;
    if (e < N) {
        size_t d = (size_t)e * N + e;
        dec[d] = comp[d];
    }
    if (g_keep[e]) {
        int r = rows[e], c = cols[e];
        size_t idx = (size_t)r * N + c;
        float v = comp[idx];
        enc[idx] = v * g_norm[r] * g_norm[c];
        dec[idx] = v;
    }
}

// random mask-pair edges (symmetric) -> dec
__global__ void k_tem(uint32_t a0, uint32_t a1, uint32_t b0, uint32_t b1,
                      const float* __restrict__ comp, float* __restrict__ dec) {
    int e = blockIdx.x * blockDim.x + threadIdx.x;
    if (e >= NNZv) return;
    float tn = (float)g_temnum;
    uint32_t p, q;
    threefry(a0, a1, 0u, (uint32_t)e, p, q);
    float u1 = bits_to_uniform(p ^ q);
    threefry(b0, b1, 0u, (uint32_t)e, p, q);
    float u2 = bits_to_uniform(p ^ q);
    int i1 = (int)floorf(u1 * tn);
    int i2 = (int)floorf(u2 * tn);
    int r = g_maskidx[i1];
    int c = g_maskidx[i2];
    size_t x = (size_t)r * N + c;
    size_t y = (size_t)c * N + r;
    dec[x] = comp[x];
    dec[y] = comp[y];
}

// ---------------- launch ---------------------------------------------------
extern "C" void kernel_launch(void* const* d_in, const int* in_sizes, int n_in,
                              void* d_out, int out_size) {
    const int*   rows  = (const int*)d_in[0];
    const int*   cols  = (const int*)d_in[1];
    // d_in[2] = adj_values: unused by the reference output
    const int*   seeds = (const int*)d_in[3];
    const float* comp  = (const float*)d_in[4];

    float* enc = (float*)d_out;
    float* dec = enc + (size_t)N * N;

    // -------- host-side Threefry key derivation (deterministic, no device work)
    // root key for jax.random.key(42) = (0, 42)
    uint32_t s10, s11, s20, s21, s30, s31, t0u, t1u, tmpa, tmpb;
    threefry(0u, 42u, 0u, 0u, s10, s11);   // k1 = split(root,3)[0]
    threefry(0u, 42u, 0u, 1u, s20, s21);   // k2 = split(root,3)[1]  (uniform u1)
    threefry(0u, 42u, 0u, 2u, s30, s31);   // k3 = split(root,3)[2]  (uniform u2)
    threefry(s10, s11, 0u, 0u, tmpa, tmpb);// randint internal split: subkey 0 (higher bits, unused: span=2^13)
    threefry(s10, s11, 0u, 1u, t0u, t1u);  // randint internal split: subkey 1 (lower bits)
    (void)tmpa; (void)tmpb;

    const int T = 256;
    k_init    <<<(N + T - 1) / T, T>>>();
    k_seed    <<<1, NSEEDS>>>(seeds);
    k_bfs0    <<<NNZv / T, T>>>(rows, cols);
    k_bfs1_deg<<<NNZv / T, T>>>(rows, cols, comp);
    k_samp    <<<(SAMP + T - 1) / T, T>>>(t0u, t1u);
    k_norm    <<<(N + T - 1) / T, T>>>();
    k_scan    <<<1, 1024>>>();

    int n4 = out_size >> 2;                       // 2*N*N is divisible by 4
    k_zero    <<<(n4 + T - 1) / T, T>>>((float4*)d_out, n4);

    k_edges   <<<NNZv / T, T>>>(rows, cols, comp, enc, dec);
    k_tem     <<<NNZv / T, T>>>(s20, s21, s30, s31, comp, dec);
}

// round 5
// speedup vs baseline: 1.0024x; 1.0024x over previous
#include <cuda_runtime.h>
#include <cstdint>

#define N      8192
#define NNZv   262144
#define NSEEDS 256
#define SAMP   7372            /* int(N * 0.9) */

// ---------------- scratch (device globals; no allocation allowed) ----------
// Packed so one memset clears everything that needs zeroing.
struct Scratch {
    int   seed0[N];
    int   mask1[N];
    int   masknodes[N];
    float deg[N];          // 0.0f == all-zero bytes
};
__device__ Scratch       g_s;
__device__ float         g_norm[N];
__device__ int           g_maskidx[N];
__device__ int           g_temnum;
__device__ unsigned char g_keep[NNZv];   // fully written by k_bfs0, no init needed

// ---------------- Threefry-2x32 (exact JAX reference rounds) ---------------
__host__ __device__ __forceinline__ void threefry(uint32_t key0, uint32_t key1,
                                                  uint32_t x0, uint32_t x1,
                                                  uint32_t &o0, uint32_t &o1) {
    uint32_t ks0 = key0, ks1 = key1, ks2 = key0 ^ key1 ^ 0x1BD11BDAu;
    x0 += ks0; x1 += ks1;
#define TF_ROT(v,d) (((v) << (d)) | ((v) >> (32 - (d))))
#define TF_R(r) { x0 += x1; x1 = TF_ROT(x1, r); x1 ^= x0; }
    TF_R(13) TF_R(15) TF_R(26) TF_R(6)   x0 += ks1; x1 += ks2 + 1u;
    TF_R(17) TF_R(29) TF_R(16) TF_R(24)  x0 += ks2; x1 += ks0 + 2u;
    TF_R(13) TF_R(15) TF_R(26) TF_R(6)   x0 += ks0; x1 += ks1 + 3u;
    TF_R(17) TF_R(29) TF_R(16) TF_R(24)  x0 += ks1; x1 += ks2 + 4u;
    TF_R(13) TF_R(15) TF_R(26) TF_R(6)   x0 += ks2; x1 += ks0 + 5u;
    o0 = x0; o1 = x1;
#undef TF_R
#undef TF_ROT
}

__device__ __forceinline__ float bits_to_uniform(uint32_t b) {
    return __uint_as_float((b >> 9) | 0x3F800000u) - 1.0f;
}

// ---------------- kernels --------------------------------------------------

// seeds -> seed0/masknodes ; random node sampling -> masknodes
__global__ void k_seed_samp(const int* __restrict__ seeds, uint32_t t0, uint32_t t1) {
    int i = blockIdx.x * blockDim.x + threadIdx.x;
    if (i < NSEEDS) { int s = seeds[i]; g_s.seed0[s] = 1; g_s.masknodes[s] = 1; }
    if (i < SAMP) {
        uint32_t a, b; threefry(t0, t1, 0u, (uint32_t)i, a, b);
        g_s.masknodes[(a ^ b) & (N - 1)] = 1;
    }
}

// depth-0: incident edges removed; mark both endpoints as next frontier
__global__ void k_bfs0(const int* __restrict__ rows, const int* __restrict__ cols) {
    int e = blockIdx.x * blockDim.x + threadIdx.x;
    if (e >= NNZv) return;
    int r = rows[e], c = cols[e];
    bool inc = (g_s.seed0[r] | g_s.seed0[c]) != 0;
    g_keep[e] = inc ? 0 : 1;
    if (inc) { g_s.mask1[r] = 1; g_s.mask1[c] = 1; }
}

// depth-1: remove edges touching frontier; accumulate row degree for survivors
__global__ void k_bfs1_deg(const int* __restrict__ rows, const int* __restrict__ cols,
                           const float* __restrict__ comp) {
    int e = blockIdx.x * blockDim.x + threadIdx.x;
    if (e >= NNZv) return;
    if (!g_keep[e]) return;
    int r = rows[e], c = cols[e];
    if (g_s.mask1[r] | g_s.mask1[c]) { g_keep[e] = 0; return; }
    atomicAdd(&g_s.deg[r], comp[(size_t)r * N + c]);
}

// fused: norm computation + compacting prefix scan over (masknodes | mask1)
__global__ void k_scan_norm() {
    __shared__ int s[1024];
    int t = threadIdx.x;
    int base = t * 8;
    int bits = 0, loc = 0;
#pragma unroll
    for (int i = 0; i < 8; i++) {
        g_norm[base + i] = rsqrtf(g_s.deg[base + i] + 1e-12f);
        int m = (g_s.masknodes[base + i] | g_s.mask1[base + i]) ? 1 : 0;
        bits |= m << i; loc += m;
    }
    s[t] = loc; __syncthreads();
    for (int off = 1; off < 1024; off <<= 1) {
        int v = (t >= off) ? s[t - off] : 0;
        __syncthreads();
        s[t] += v;
        __syncthreads();
    }
    int pos = s[t] - loc;            // exclusive prefix
    if (t == 1023) g_temnum = s[1023];
#pragma unroll
    for (int i = 0; i < 8; i++)
        if ((bits >> i) & 1) g_maskidx[pos++] = base + i;
}

// fused scatter: [0,NNZ) kept edges + diagonal, [NNZ,2*NNZ) random mask pairs
__global__ void k_scatter(const int* __restrict__ rows, const int* __restrict__ cols,
                          const float* __restrict__ comp,
                          float* __restrict__ enc, float* __restrict__ dec,
                          uint32_t a0, uint32_t a1, uint32_t b0, uint32_t b1) {
    int i = blockIdx.x * blockDim.x + threadIdx.x;
    if (i < NNZv) {
        if (i < N) {
            size_t d = (size_t)i * N + i;
            dec[d] = comp[d];
        }
        if (g_keep[i]) {
            int r = rows[i], c = cols[i];
            size_t idx = (size_t)r * N + c;
            float v = comp[idx];
            enc[idx] = v * g_norm[r] * g_norm[c];
            dec[idx] = v;
        }
    } else {
        int e = i - NNZv;
        float tn = (float)g_temnum;
        uint32_t p, q;
        threefry(a0, a1, 0u, (uint32_t)e, p, q);
        float u1 = bits_to_uniform(p ^ q);
        threefry(b0, b1, 0u, (uint32_t)e, p, q);
        float u2 = bits_to_uniform(p ^ q);
        int r = g_maskidx[(int)floorf(u1 * tn)];
        int c = g_maskidx[(int)floorf(u2 * tn)];
        size_t x = (size_t)r * N + c;
        size_t y = (size_t)c * N + r;
        dec[x] = comp[x];
        dec[y] = comp[y];
    }
}

// ---------------- launch ---------------------------------------------------
extern "C" void kernel_launch(void* const* d_in, const int* in_sizes, int n_in,
                              void* d_out, int out_size) {
    const int*   rows  = (const int*)d_in[0];
    const int*   cols  = (const int*)d_in[1];
    // d_in[2] = adj_values: unused by the reference output
    const int*   seeds = (const int*)d_in[3];
    const float* comp  = (const float*)d_in[4];

    float* enc = (float*)d_out;
    float* dec = enc + (size_t)N * N;

    // -------- lazily-created resources (no device memory; work is unchanged)
    static cudaStream_t s2 = nullptr;
    static cudaEvent_t  evFork = nullptr, evJoin = nullptr;
    static void* scratch_ptr = nullptr;
    if (s2 == nullptr) {
        cudaStreamCreateWithFlags(&s2, cudaStreamNonBlocking);
        cudaEventCreateWithFlags(&evFork, cudaEventDisableTiming);
        cudaEventCreateWithFlags(&evJoin, cudaEventDisableTiming);
        cudaGetSymbolAddress(&scratch_ptr, g_s);
    }

    // -------- host-side Threefry key derivation (root key (0,42))
    uint32_t s10, s11, s20, s21, s30, s31, t0u, t1u, tmpa, tmpb;
    threefry(0u, 42u, 0u, 0u, s10, s11);   // k1 = split(root,3)[0]
    threefry(0u, 42u, 0u, 1u, s20, s21);   // k2 (uniform u1)
    threefry(0u, 42u, 0u, 2u, s30, s31);   // k3 (uniform u2)
    threefry(s10, s11, 0u, 0u, tmpa, tmpb);// randint split: hi-bits subkey (unused: span=2^13)
    threefry(s10, s11, 0u, 1u, t0u, t1u);  // randint split: lo-bits subkey
    (void)tmpa; (void)tmpb;

    const int T = 256;

    // ---- fork: 512 MB output zero-fill runs concurrently with the mask chain
    cudaEventRecord(evFork, 0);
    cudaStreamWaitEvent(s2, evFork, 0);
    cudaMemsetAsync(d_out, 0, (size_t)out_size * sizeof(float), s2);

    // ---- main-stream chain: scratch clear -> seeds/samp -> BFS -> scan/norm
    cudaMemsetAsync(scratch_ptr, 0, sizeof(Scratch), 0);
    k_seed_samp<<<(SAMP + T - 1) / T, T>>>(seeds, t0u, t1u);
    k_bfs0     <<<NNZv / T, T>>>(rows, cols);
    k_bfs1_deg <<<NNZv / T, T>>>(rows, cols, comp);
    k_scan_norm<<<1, 1024>>>();

    // ---- join: scatters need the zero-filled output
    cudaEventRecord(evJoin, s2);
    cudaStreamWaitEvent(0, evJoin, 0);

    k_scatter<<<(2 * NNZv) / T, T>>>(rows, cols, comp, enc, dec,
                                     s20, s21, s30, s31);
}

// round 6
// speedup vs baseline: 1.0252x; 1.0228x over previous
#include <cuda_runtime.h>
#include <cstdint>

#define N      8192
#define NNZv   262144
#define NSEEDS 256
#define SAMP   7372            /* int(N * 0.9) */

// ---------------- scratch (device globals; no allocation allowed) ----------
struct Scratch {
    int   seed0[N];
    int   mask1[N];
    int   masknodes[N];
    float deg[N];          // 0.0f == all-zero bytes
};
__device__ Scratch       g_s;
__device__ float         g_norm[N];
__device__ int           g_maskidx[N];
__device__ int           g_temnum;
__device__ unsigned char g_keep[NNZv];   // fully written by k_bfs0

// ---------------- Threefry-2x32 (exact JAX reference rounds) ---------------
__host__ __device__ __forceinline__ void threefry(uint32_t key0, uint32_t key1,
                                                  uint32_t x0, uint32_t x1,
                                                  uint32_t &o0, uint32_t &o1) {
    uint32_t ks0 = key0, ks1 = key1, ks2 = key0 ^ key1 ^ 0x1BD11BDAu;
    x0 += ks0; x1 += ks1;
#define TF_ROT(v,d) (((v) << (d)) | ((v) >> (32 - (d))))
#define TF_R(r) { x0 += x1; x1 = TF_ROT(x1, r); x1 ^= x0; }
    TF_R(13) TF_R(15) TF_R(26) TF_R(6)   x0 += ks1; x1 += ks2 + 1u;
    TF_R(17) TF_R(29) TF_R(16) TF_R(24)  x0 += ks2; x1 += ks0 + 2u;
    TF_R(13) TF_R(15) TF_R(26) TF_R(6)   x0 += ks0; x1 += ks1 + 3u;
    TF_R(17) TF_R(29) TF_R(16) TF_R(24)  x0 += ks1; x1 += ks2 + 4u;
    TF_R(13) TF_R(15) TF_R(26) TF_R(6)   x0 += ks2; x1 += ks0 + 5u;
    o0 = x0; o1 = x1;
#undef TF_R
#undef TF_ROT
}

__device__ __forceinline__ float bits_to_uniform(uint32_t b) {
    return __uint_as_float((b >> 9) | 0x3F800000u) - 1.0f;
}

// ---------------- kernels --------------------------------------------------

// fast coalesced zero-fill: one float4 per thread, no tail (n4 % blockDim == 0)
__global__ void k_zero(float4* __restrict__ out) {
    size_t i = (size_t)blockIdx.x * blockDim.x + threadIdx.x;
    out[i] = make_float4(0.f, 0.f, 0.f, 0.f);
}

// seeds -> seed0/masknodes ; random node sampling -> masknodes
__global__ void k_seed_samp(const int* __restrict__ seeds, uint32_t t0, uint32_t t1) {
    int i = blockIdx.x * blockDim.x + threadIdx.x;
    if (i < NSEEDS) { int s = seeds[i]; g_s.seed0[s] = 1; g_s.masknodes[s] = 1; }
    if (i < SAMP) {
        uint32_t a, b; threefry(t0, t1, 0u, (uint32_t)i, a, b);
        g_s.masknodes[(a ^ b) & (N - 1)] = 1;
    }
}

// depth-0: incident edges removed; mark both endpoints as next frontier
__global__ void k_bfs0(const int* __restrict__ rows, const int* __restrict__ cols) {
    int e = blockIdx.x * blockDim.x + threadIdx.x;
    if (e >= NNZv) return;
    int r = rows[e], c = cols[e];
    bool inc = (g_s.seed0[r] | g_s.seed0[c]) != 0;
    g_keep[e] = inc ? 0 : 1;
    if (inc) { g_s.mask1[r] = 1; g_s.mask1[c] = 1; }
}

// depth-1: remove edges touching frontier; accumulate row degree for survivors
__global__ void k_bfs1_deg(const int* __restrict__ rows, const int* __restrict__ cols,
                           const float* __restrict__ comp) {
    int e = blockIdx.x * blockDim.x + threadIdx.x;
    if (e >= NNZv) return;
    if (!g_keep[e]) return;
    int r = rows[e], c = cols[e];
    if (g_s.mask1[r] | g_s.mask1[c]) { g_keep[e] = 0; return; }
    atomicAdd(&g_s.deg[r], comp[(size_t)r * N + c]);
}

// fused: norm computation + compacting prefix scan (warp-shuffle version)
__global__ void k_scan_norm() {
    __shared__ int warp_sums[32];
    int t    = threadIdx.x;
    int lane = t & 31;
    int wid  = t >> 5;
    int base = t * 8;

    int bits = 0, loc = 0;
#pragma unroll
    for (int i = 0; i < 8; i++) {
        g_norm[base + i] = rsqrtf(g_s.deg[base + i] + 1e-12f);
        int m = (g_s.masknodes[base + i] | g_s.mask1[base + i]) ? 1 : 0;
        bits |= m << i; loc += m;
    }

    // warp inclusive scan of loc
    int inc = loc;
#pragma unroll
    for (int off = 1; off < 32; off <<= 1) {
        int v = __shfl_up_sync(0xFFFFFFFFu, inc, off);
        if (lane >= off) inc += v;
    }
    if (lane == 31) warp_sums[wid] = inc;
    __syncthreads();

    // warp 0 scans the 32 warp totals
    if (wid == 0) {
        int v = warp_sums[lane];
        int s = v;
#pragma unroll
        for (int off = 1; off < 32; off <<= 1) {
            int u = __shfl_up_sync(0xFFFFFFFFu, s, off);
            if (lane >= off) s += u;
        }
        warp_sums[lane] = s - v;     // exclusive warp offset
        if (lane == 31) g_temnum = s;
    }
    __syncthreads();

    int pos = warp_sums[wid] + inc - loc;   // global exclusive prefix
#pragma unroll
    for (int i = 0; i < 8; i++)
        if ((bits >> i) & 1) g_maskidx[pos++] = base + i;
}

// fused scatter: [0,NNZ) kept edges + diagonal, [NNZ,2*NNZ) random mask pairs
__global__ void k_scatter(const int* __restrict__ rows, const int* __restrict__ cols,
                          const float* __restrict__ comp,
                          float* __restrict__ enc, float* __restrict__ dec,
                          uint32_t a0, uint32_t a1, uint32_t b0, uint32_t b1) {
    int i = blockIdx.x * blockDim.x + threadIdx.x;
    if (i < NNZv) {
        if (i < N) {
            size_t d = (size_t)i * N + i;
            dec[d] = comp[d];
        }
        if (g_keep[i]) {
            int r = rows[i], c = cols[i];
            size_t idx = (size_t)r * N + c;
            float v = comp[idx];
            enc[idx] = v * g_norm[r] * g_norm[c];
            dec[idx] = v;
        }
    } else {
        int e = i - NNZv;
        float tn = (float)g_temnum;
        uint32_t p, q;
        threefry(a0, a1, 0u, (uint32_t)e, p, q);
        float u1 = bits_to_uniform(p ^ q);
        threefry(b0, b1, 0u, (uint32_t)e, p, q);
        float u2 = bits_to_uniform(p ^ q);
        int r = g_maskidx[(int)floorf(u1 * tn)];
        int c = g_maskidx[(int)floorf(u2 * tn)];
        size_t x = (size_t)r * N + c;
        size_t y = (size_t)c * N + r;
        dec[x] = comp[x];
        dec[y] = comp[y];
    }
}

// ---------------- launch ---------------------------------------------------
extern "C" void kernel_launch(void* const* d_in, const int* in_sizes, int n_in,
                              void* d_out, int out_size) {
    const int*   rows  = (const int*)d_in[0];
    const int*   cols  = (const int*)d_in[1];
    // d_in[2] = adj_values: unused by the reference output
    const int*   seeds = (const int*)d_in[3];
    const float* comp  = (const float*)d_in[4];

    float* enc = (float*)d_out;
    float* dec = enc + (size_t)N * N;

    // -------- lazily-created resources (no device memory; work unchanged)
    static cudaStream_t s2 = nullptr;
    static cudaEvent_t  evFork = nullptr, evJoin = nullptr;
    static void* scratch_ptr = nullptr;
    if (s2 == nullptr) {
        cudaStreamCreateWithFlags(&s2, cudaStreamNonBlocking);
        cudaEventCreateWithFlags(&evFork, cudaEventDisableTiming);
        cudaEventCreateWithFlags(&evJoin, cudaEventDisableTiming);
        cudaGetSymbolAddress(&scratch_ptr, g_s);
    }

    // -------- host-side Threefry key derivation (root key (0,42))
    uint32_t s10, s11, s20, s21, s30, s31, t0u, t1u, tmpa, tmpb;
    threefry(0u, 42u, 0u, 0u, s10, s11);   // k1 = split(root,3)[0]
    threefry(0u, 42u, 0u, 1u, s20, s21);   // k2 (uniform u1)
    threefry(0u, 42u, 0u, 2u, s30, s31);   // k3 (uniform u2)
    threefry(s10, s11, 0u, 0u, tmpa, tmpb);// randint split: hi-bits subkey (unused)
    threefry(s10, s11, 0u, 1u, t0u, t1u);  // randint split: lo-bits subkey
    (void)tmpa; (void)tmpb;

    const int T = 256;

    // ---- fork: fast kernel zero-fill (512 MB) concurrent with the mask chain
    cudaEventRecord(evFork, 0);
    cudaStreamWaitEvent(s2, evFork, 0);
    int n4 = out_size >> 2;                        // 2*N*N / 4, divisible by 256
    k_zero<<<n4 / T, T, 0, s2>>>((float4*)d_out);

    // ---- main-stream chain
    cudaMemsetAsync(scratch_ptr, 0, sizeof(Scratch), 0);
    k_seed_samp<<<(SAMP + T - 1) / T, T>>>(seeds, t0u, t1u);
    k_bfs0     <<<NNZv / T, T>>>(rows, cols);
    k_bfs1_deg <<<NNZv / T, T>>>(rows, cols, comp);
    k_scan_norm<<<1, 1024>>>();

    // ---- join: scatters need the zero-filled output
    cudaEventRecord(evJoin, s2);
    cudaStreamWaitEvent(0, evJoin, 0);

    k_scatter<<<(2 * NNZv) / T, T>>>(rows, cols, comp, enc, dec,
                                     s20, s21, s30, s31);
}